// round 9
// baseline (speedup 1.0000x reference)
#include <cuda_runtime.h>
#include <cuda_bf16.h>
#include <cstdint>

// ---------------------------------------------------------------------------
// GCN 2-layer: out = A_norm( relu( A_norm(x W1) + b1 ) W2 ) + b2
// A_norm includes self-loops, norm = dinv[src]*dinv[dst], dinv = rsqrt(deg).
// edge_index is INT32 on device (JAX x64 disabled downcasts int64 -> int32).
// ---------------------------------------------------------------------------

#define N_NODES 50000
#define F0 512
#define F1 128
#define F2 64

// Scratch (allocation-free rules: device globals)
__device__ float g_h1  [(size_t)N_NODES * F1];   // x @ W1
__device__ float g_agg1[(size_t)N_NODES * F1];   // aggregated layer-1
__device__ float g_h2  [(size_t)N_NODES * F2];   // relu(agg1) @ W2
__device__ float g_dinv[N_NODES];                // rsqrt(deg)

// ---------------------------------------------------------------------------
// Degree / norm kernels
// ---------------------------------------------------------------------------
__global__ void k_init_deg(float* deg, int n) {
    int i = blockIdx.x * blockDim.x + threadIdx.x;
    if (i < n) deg[i] = 1.0f;  // self-loop
}

__global__ void k_count_deg(const int* __restrict__ dst, int E, float* deg) {
    int e = blockIdx.x * blockDim.x + threadIdx.x;
    if (e < E) atomicAdd(&deg[dst[e]], 1.0f);
}

__global__ void k_deg_to_dinv(float* deg, int n) {
    int i = blockIdx.x * blockDim.x + threadIdx.x;
    if (i < n) deg[i] = rsqrtf(deg[i]);
}

// ---------------------------------------------------------------------------
// Register-tiled SGEMM: C[M,N] = A[M,K] @ B[K,N]   (fp32)
// ---------------------------------------------------------------------------
template <int BM, int BN, int BK, int TM, int TN>
__global__ void k_sgemm(const float* __restrict__ A, const float* __restrict__ B,
                        float* __restrict__ C, int M, int N, int K) {
    __shared__ float As[BK][BM];
    __shared__ float Bs[BK][BN];
    constexpr int THREADS = (BM / TM) * (BN / TN);

    const int tid = threadIdx.x;
    const int tx  = tid % (BN / TN);
    const int ty  = tid / (BN / TN);
    const int rowBase = blockIdx.y * BM;
    const int colBase = blockIdx.x * BN;

    float acc[TM][TN];
#pragma unroll
    for (int i = 0; i < TM; i++)
#pragma unroll
        for (int j = 0; j < TN; j++) acc[i][j] = 0.0f;

    for (int k0 = 0; k0 < K; k0 += BK) {
        // Load A tile (BM x BK) as float4, store transposed As[k][m]
#pragma unroll
        for (int idx = tid; idx < BM * BK / 4; idx += THREADS) {
            int r  = idx / (BK / 4);
            int c4 = idx % (BK / 4);
            float4 v = make_float4(0.f, 0.f, 0.f, 0.f);
            int gr = rowBase + r;
            if (gr < M)
                v = *reinterpret_cast<const float4*>(&A[(size_t)gr * K + k0 + c4 * 4]);
            As[c4 * 4 + 0][r] = v.x;
            As[c4 * 4 + 1][r] = v.y;
            As[c4 * 4 + 2][r] = v.z;
            As[c4 * 4 + 3][r] = v.w;
        }
        // Load B tile (BK x BN) as float4
#pragma unroll
        for (int idx = tid; idx < BK * BN / 4; idx += THREADS) {
            int r  = idx / (BN / 4);
            int c4 = idx % (BN / 4);
            *reinterpret_cast<float4*>(&Bs[r][c4 * 4]) =
                *reinterpret_cast<const float4*>(&B[(size_t)(k0 + r) * N + colBase + c4 * 4]);
        }
        __syncthreads();

#pragma unroll
        for (int k = 0; k < BK; k++) {
            float ra[TM], rb[TN];
#pragma unroll
            for (int i = 0; i < TM; i++) ra[i] = As[k][ty * TM + i];
#pragma unroll
            for (int j = 0; j < TN; j++) rb[j] = Bs[k][tx * TN + j];
#pragma unroll
            for (int i = 0; i < TM; i++)
#pragma unroll
                for (int j = 0; j < TN; j++) acc[i][j] += ra[i] * rb[j];
        }
        __syncthreads();
    }

#pragma unroll
    for (int i = 0; i < TM; i++) {
        int gr = rowBase + ty * TM + i;
        if (gr >= M) continue;
#pragma unroll
        for (int j = 0; j < TN; j += 4) {
            float4 v = make_float4(acc[i][j], acc[i][j + 1], acc[i][j + 2], acc[i][j + 3]);
            *reinterpret_cast<float4*>(&C[(size_t)gr * N + colBase + tx * TN + j]) = v;
        }
    }
}

// ---------------------------------------------------------------------------
// Aggregation init: out[i,f] = h[i,f] * dinv[i]^2  (self-loop term) [+ bias]
// ---------------------------------------------------------------------------
template <int F, bool ADD_BIAS>
__global__ void k_agg_init(const float* __restrict__ h, const float* __restrict__ dinv,
                           const float* __restrict__ bias, float* __restrict__ out, int n_elems) {
    int i = blockIdx.x * blockDim.x + threadIdx.x;
    if (i >= n_elems) return;
    int node = i / F;
    float d = dinv[node];
    float v = h[i] * d * d;
    if (ADD_BIAS) v += bias[i % F];
    out[i] = v;
}

// ---------------------------------------------------------------------------
// Edge scatter-add: one warp per edge, VEC floats per lane (F = 32*VEC)
// ---------------------------------------------------------------------------
template <int VEC>
__global__ void k_edge_agg(const int* __restrict__ src, const int* __restrict__ dst,
                           const float* __restrict__ dinv, const float* __restrict__ h,
                           float* __restrict__ out, int E) {
    constexpr int F = 32 * VEC;
    long long gtid = (long long)blockIdx.x * blockDim.x + threadIdx.x;
    int e    = (int)(gtid >> 5);
    int lane = (int)(gtid & 31);
    if (e >= E) return;
    int s = src[e];
    int d = dst[e];
    float norm = dinv[s] * dinv[d];

    const float* hp = h + (size_t)s * F + lane * VEC;
    float*       op = out + (size_t)d * F + lane * VEC;

    if (VEC == 4) {
        float4 v = *reinterpret_cast<const float4*>(hp);
        atomicAdd(op + 0, v.x * norm);
        atomicAdd(op + 1, v.y * norm);
        atomicAdd(op + 2, v.z * norm);
        atomicAdd(op + 3, v.w * norm);
    } else {  // VEC == 2
        float2 v = *reinterpret_cast<const float2*>(hp);
        atomicAdd(op + 0, v.x * norm);
        atomicAdd(op + 1, v.y * norm);
    }
}

// ---------------------------------------------------------------------------
// ReLU + bias in place (layer 1 epilogue)
// ---------------------------------------------------------------------------
template <int F>
__global__ void k_relu_bias(float* __restrict__ a, const float* __restrict__ bias, int n_elems) {
    int i = blockIdx.x * blockDim.x + threadIdx.x;
    if (i >= n_elems) return;
    a[i] = fmaxf(a[i] + bias[i % F], 0.0f);
}

// ---------------------------------------------------------------------------
// Launcher — bind inputs BY ELEMENT COUNT (robust to metadata ordering):
//   x: 25,600,000   edge_index: 3,200,000 (int32)   W1: 65,536
//   b1: 128         W2: 8,192                       b2: 64
// ---------------------------------------------------------------------------
extern "C" void kernel_launch(void* const* d_in, const int* in_sizes, int n_in,
                              void* d_out, int out_size) {
    const float* x  = nullptr;
    const int*   ei = nullptr;
    const float* W1 = nullptr;
    const float* b1 = nullptr;
    const float* W2 = nullptr;
    const float* b2 = nullptr;

    for (int i = 0; i < n_in; i++) {
        switch (in_sizes[i]) {
            case N_NODES * F0: x  = (const float*)d_in[i]; break;  // 25.6M
            case 2 * 1600000:  ei = (const int*)  d_in[i]; break;  // 3.2M (int32!)
            case F0 * F1:      W1 = (const float*)d_in[i]; break;  // 65536
            case F1:           b1 = (const float*)d_in[i]; break;  // 128
            case F1 * F2:      W2 = (const float*)d_in[i]; break;  // 8192
            case F2:           b2 = (const float*)d_in[i]; break;  // 64
            default: break;
        }
    }

    float* out = (float*)d_out;
    const int N = N_NODES;
    const int E = 1600000;
    const int* src = ei;
    const int* dst = ei + E;

    float *h1, *agg1, *h2, *dinv;
    cudaGetSymbolAddress((void**)&h1,   g_h1);
    cudaGetSymbolAddress((void**)&agg1, g_agg1);
    cudaGetSymbolAddress((void**)&h2,   g_h2);
    cudaGetSymbolAddress((void**)&dinv, g_dinv);

    const int T = 256;

    // 1) degrees -> dinv
    k_init_deg<<<(N + T - 1) / T, T>>>(dinv, N);
    k_count_deg<<<(E + T - 1) / T, T>>>(dst, E, dinv);
    k_deg_to_dinv<<<(N + T - 1) / T, T>>>(dinv, N);

    // 2) GEMM1: h1 = x @ W1   (M=N_NODES, N=128, K=512)
    {
        dim3 grid(F1 / 128, (N + 127) / 128);
        k_sgemm<128, 128, 16, 8, 8><<<grid, 256>>>(x, W1, h1, N, F1, F0);
    }

    // 3) layer-1 aggregation: init with self-loop term, then edge scatter
    k_agg_init<F1, false><<<((N * F1) + T - 1) / T, T>>>(h1, dinv, nullptr, agg1, N * F1);
    {
        long long threads = (long long)E * 32;
        int blocks = (int)((threads + T - 1) / T);
        k_edge_agg<4><<<blocks, T>>>(src, dst, dinv, h1, agg1, E);
    }

    // 4) relu(agg1 + b1) in place
    k_relu_bias<F1><<<((N * F1) + T - 1) / T, T>>>(agg1, b1, N * F1);

    // 5) GEMM2: h2 = agg1 @ W2  (M=N_NODES, N=64, K=128)
    {
        dim3 grid(F2 / 64, (N + 127) / 128);
        k_sgemm<128, 64, 16, 8, 4><<<grid, 256>>>(agg1, W2, h2, N, F2, F1);
    }

    // 6) layer-2 aggregation straight into d_out (init includes b2 + self-loop)
    k_agg_init<F2, true><<<((N * F2) + T - 1) / T, T>>>(h2, dinv, b2, out, N * F2);
    {
        long long threads = (long long)E * 32;
        int blocks = (int)((threads + T - 1) / T);
        k_edge_agg<2><<<blocks, T>>>(src, dst, dinv, h2, out, E);
    }
}

// round 10
// speedup vs baseline: 1.8858x; 1.8858x over previous
#include <cuda_runtime.h>
#include <cuda_bf16.h>
#include <cstdint>

// ---------------------------------------------------------------------------
// GCN 2-layer: out = A_norm( relu( A_norm(x W1) + b1 ) W2 ) + b2
// A_norm = D^-1/2 (A+I) D^-1/2.  Strategy:
//   - GEMM epilogue prescales rows by dinv  ->  hs = (X W) * dinv[row]
//   - CSR-by-dst gather:  out[n] = dinv[n]*(sum_{s in N(n)} hs[s] + hs[n]) + b
//   - bias/relu fused into the aggregation epilogue
//   - GEMM inner loop uses packed fma.rn.f32x2 (Blackwell dual-rate FP32)
// edge_index is INT32 on device (JAX x64 disabled).
// ---------------------------------------------------------------------------

#define N_NODES 50000
#define N_EDGES 1600000
#define F0 512
#define F1 128
#define F2 64

// Scratch (allocation-free rules: device globals)
__device__ float g_h1s [(size_t)N_NODES * F1];   // (x@W1)*dinv
__device__ float g_r1  [(size_t)N_NODES * F1];   // relu(agg1+b1)
__device__ float g_h2s [(size_t)N_NODES * F2];   // (r1@W2)*dinv
__device__ float g_dinv[N_NODES];
__device__ int   g_cnt [N_NODES];
__device__ int   g_row [N_NODES + 1];
__device__ int   g_cur [N_NODES];
__device__ int   g_csr [N_EDGES];

// ---------------------------------------------------------------------------
// f32x2 packed-FMA helpers
// ---------------------------------------------------------------------------
__device__ __forceinline__ unsigned long long pack2(float lo, float hi) {
    unsigned long long r;
    asm("mov.b64 %0, {%1, %2};" : "=l"(r) : "f"(lo), "f"(hi));
    return r;
}
__device__ __forceinline__ void fma2(unsigned long long& d, unsigned long long a,
                                     unsigned long long b) {
    asm("fma.rn.f32x2 %0, %1, %2, %3;" : "=l"(d) : "l"(a), "l"(b), "l"(d));
}
__device__ __forceinline__ float2 unpack2(unsigned long long v) {
    float2 f;
    asm("mov.b64 {%0, %1}, %2;" : "=f"(f.x), "=f"(f.y) : "l"(v));
    return f;
}

// ---------------------------------------------------------------------------
// Degree / CSR build
// ---------------------------------------------------------------------------
__global__ void k_zero_cnt(int* cnt, int n) {
    int i = blockIdx.x * blockDim.x + threadIdx.x;
    if (i < n) cnt[i] = 0;
}
__global__ void k_count(const int* __restrict__ dst, int E, int* cnt) {
    int e = blockIdx.x * blockDim.x + threadIdx.x;
    if (e < E) atomicAdd(&cnt[dst[e]], 1);
}
__global__ void k_dinv(const int* __restrict__ cnt, float* __restrict__ dinv, int n) {
    int i = blockIdx.x * blockDim.x + threadIdx.x;
    if (i < n) dinv[i] = rsqrtf((float)(cnt[i] + 1));  // +1 self-loop
}

// One-block exclusive scan over cnt -> row_start & cursor.  n <= 1024*chunk.
__global__ void k_scan(const int* __restrict__ cnt, int* __restrict__ row_start,
                       int* __restrict__ cursor, int n, int total) {
    __shared__ int wsum[32];
    const int T = 1024;
    int tid = threadIdx.x;
    int chunk = (n + T - 1) / T;
    int begin = tid * chunk;
    int end   = begin + chunk; if (end > n) end = n; if (begin > n) begin = n;

    int s = 0;
    for (int i = begin; i < end; i++) s += cnt[i];

    int lane = tid & 31, wid = tid >> 5;
    int v = s;
#pragma unroll
    for (int o = 1; o < 32; o <<= 1) {
        int t = __shfl_up_sync(0xffffffffu, v, o);
        if (lane >= o) v += t;
    }
    if (lane == 31) wsum[wid] = v;
    __syncthreads();
    if (wid == 0) {
        int w = wsum[lane];
#pragma unroll
        for (int o = 1; o < 32; o <<= 1) {
            int t = __shfl_up_sync(0xffffffffu, w, o);
            if (lane >= o) w += t;
        }
        wsum[lane] = w;
    }
    __syncthreads();
    int excl = (v - s) + (wid ? wsum[wid - 1] : 0);

    int run = excl;
    for (int i = begin; i < end; i++) {
        row_start[i] = run;
        cursor[i]    = run;
        run += cnt[i];
    }
    if (tid == 0) row_start[n] = total;
}

__global__ void k_fill(const int* __restrict__ src, const int* __restrict__ dst,
                       int E, int* __restrict__ cursor, int* __restrict__ csr) {
    int e = blockIdx.x * blockDim.x + threadIdx.x;
    if (e >= E) return;
    int d = dst[e];
    int pos = atomicAdd(&cursor[d], 1);
    csr[pos] = src[e];
}

// ---------------------------------------------------------------------------
// Register-tiled SGEMM with f32x2 packed FMA and row-scale epilogue:
//   C[r, c] = (A[r,:] @ B[:,c]) * rowscale[r]
// ---------------------------------------------------------------------------
template <int BM, int BN, int BK, int TM, int TN>
__global__ void k_sgemm(const float* __restrict__ A, const float* __restrict__ B,
                        float* __restrict__ C, const float* __restrict__ rowscale,
                        int M, int N, int K) {
    __shared__ float As[BK][BM];
    __shared__ float Bs[BK][BN];
    constexpr int THREADS = (BM / TM) * (BN / TN);
    constexpr int TN2 = TN / 2;

    const int tid = threadIdx.x;
    const int tx  = tid % (BN / TN);
    const int ty  = tid / (BN / TN);
    const int rowBase = blockIdx.y * BM;
    const int colBase = blockIdx.x * BN;

    unsigned long long acc2[TM][TN2];
#pragma unroll
    for (int i = 0; i < TM; i++)
#pragma unroll
        for (int j = 0; j < TN2; j++) acc2[i][j] = 0ull;

    for (int k0 = 0; k0 < K; k0 += BK) {
#pragma unroll
        for (int idx = tid; idx < BM * BK / 4; idx += THREADS) {
            int r  = idx / (BK / 4);
            int c4 = idx % (BK / 4);
            float4 v = make_float4(0.f, 0.f, 0.f, 0.f);
            int gr = rowBase + r;
            if (gr < M)
                v = *reinterpret_cast<const float4*>(&A[(size_t)gr * K + k0 + c4 * 4]);
            As[c4 * 4 + 0][r] = v.x;
            As[c4 * 4 + 1][r] = v.y;
            As[c4 * 4 + 2][r] = v.z;
            As[c4 * 4 + 3][r] = v.w;
        }
#pragma unroll
        for (int idx = tid; idx < BK * BN / 4; idx += THREADS) {
            int r  = idx / (BN / 4);
            int c4 = idx % (BN / 4);
            *reinterpret_cast<float4*>(&Bs[r][c4 * 4]) =
                *reinterpret_cast<const float4*>(&B[(size_t)(k0 + r) * N + colBase + c4 * 4]);
        }
        __syncthreads();

#pragma unroll
        for (int k = 0; k < BK; k++) {
            float ra[TM];
            unsigned long long rb2[TN2];
#pragma unroll
            for (int i = 0; i < TM; i++) ra[i] = As[k][ty * TM + i];
            const unsigned long long* bp =
                reinterpret_cast<const unsigned long long*>(&Bs[k][tx * TN]);
#pragma unroll
            for (int j = 0; j < TN2; j++) rb2[j] = bp[j];
#pragma unroll
            for (int i = 0; i < TM; i++) {
                unsigned long long a2 = pack2(ra[i], ra[i]);
#pragma unroll
                for (int j = 0; j < TN2; j++) fma2(acc2[i][j], a2, rb2[j]);
            }
        }
        __syncthreads();
    }

#pragma unroll
    for (int i = 0; i < TM; i++) {
        int gr = rowBase + ty * TM + i;
        if (gr >= M) continue;
        float sc = rowscale ? rowscale[gr] : 1.0f;
#pragma unroll
        for (int j = 0; j < TN2; j += 2) {
            float2 a = unpack2(acc2[i][j]);
            float2 b = unpack2(acc2[i][j + 1]);
            float4 v = make_float4(a.x * sc, a.y * sc, b.x * sc, b.y * sc);
            *reinterpret_cast<float4*>(&C[(size_t)gr * N + colBase + tx * TN + j * 2]) = v;
        }
    }
}

// ---------------------------------------------------------------------------
// CSR gather-aggregate: one warp per node, VEC floats per lane (F = 32*VEC)
//   out[n] = dinv[n] * ( sum_{e} hs[csr[e]] + hs[n] ) + bias   [relu]
// ---------------------------------------------------------------------------
template <int VEC, bool RELU>
__global__ void k_agg_csr(const float* __restrict__ hs, const int* __restrict__ row_start,
                          const int* __restrict__ csr, const float* __restrict__ dinv,
                          const float* __restrict__ bias, float* __restrict__ out, int n) {
    constexpr int F = 32 * VEC;
    int warp = (blockIdx.x * blockDim.x + threadIdx.x) >> 5;
    int lane = threadIdx.x & 31;
    if (warp >= n) return;

    int e0 = row_start[warp];
    int e1 = row_start[warp + 1];

    float acc[VEC];
    // self term
    if (VEC == 4) {
        float4 v = *reinterpret_cast<const float4*>(hs + (size_t)warp * F + lane * 4);
        acc[0] = v.x; acc[1] = v.y; acc[2] = v.z; acc[3] = v.w;
    } else {
        float2 v = *reinterpret_cast<const float2*>(hs + (size_t)warp * F + lane * 2);
        acc[0] = v.x; acc[1] = v.y;
    }

    int e = e0;
    for (; e + 4 <= e1; e += 4) {
        int s0 = csr[e], s1 = csr[e + 1], s2 = csr[e + 2], s3 = csr[e + 3];
        if (VEC == 4) {
            float4 v0 = *reinterpret_cast<const float4*>(hs + (size_t)s0 * F + lane * 4);
            float4 v1 = *reinterpret_cast<const float4*>(hs + (size_t)s1 * F + lane * 4);
            float4 v2 = *reinterpret_cast<const float4*>(hs + (size_t)s2 * F + lane * 4);
            float4 v3 = *reinterpret_cast<const float4*>(hs + (size_t)s3 * F + lane * 4);
            acc[0] += v0.x + v1.x + v2.x + v3.x;
            acc[1] += v0.y + v1.y + v2.y + v3.y;
            acc[2] += v0.z + v1.z + v2.z + v3.z;
            acc[3] += v0.w + v1.w + v2.w + v3.w;
        } else {
            float2 v0 = *reinterpret_cast<const float2*>(hs + (size_t)s0 * F + lane * 2);
            float2 v1 = *reinterpret_cast<const float2*>(hs + (size_t)s1 * F + lane * 2);
            float2 v2 = *reinterpret_cast<const float2*>(hs + (size_t)s2 * F + lane * 2);
            float2 v3 = *reinterpret_cast<const float2*>(hs + (size_t)s3 * F + lane * 2);
            acc[0] += v0.x + v1.x + v2.x + v3.x;
            acc[1] += v0.y + v1.y + v2.y + v3.y;
        }
    }
    for (; e < e1; e++) {
        int s = csr[e];
        if (VEC == 4) {
            float4 v = *reinterpret_cast<const float4*>(hs + (size_t)s * F + lane * 4);
            acc[0] += v.x; acc[1] += v.y; acc[2] += v.z; acc[3] += v.w;
        } else {
            float2 v = *reinterpret_cast<const float2*>(hs + (size_t)s * F + lane * 2);
            acc[0] += v.x; acc[1] += v.y;
        }
    }

    float dn = dinv[warp];
    float* op = out + (size_t)warp * F + lane * VEC;
    if (VEC == 4) {
        float4 bsv = *reinterpret_cast<const float4*>(bias + lane * 4);
        float4 r = make_float4(acc[0] * dn + bsv.x, acc[1] * dn + bsv.y,
                               acc[2] * dn + bsv.z, acc[3] * dn + bsv.w);
        if (RELU) {
            r.x = fmaxf(r.x, 0.f); r.y = fmaxf(r.y, 0.f);
            r.z = fmaxf(r.z, 0.f); r.w = fmaxf(r.w, 0.f);
        }
        *reinterpret_cast<float4*>(op) = r;
    } else {
        float2 bsv = *reinterpret_cast<const float2*>(bias + lane * 2);
        float2 r = make_float2(acc[0] * dn + bsv.x, acc[1] * dn + bsv.y);
        if (RELU) { r.x = fmaxf(r.x, 0.f); r.y = fmaxf(r.y, 0.f); }
        *reinterpret_cast<float2*>(op) = r;
    }
}

// ---------------------------------------------------------------------------
// Launcher — bind inputs BY ELEMENT COUNT
// ---------------------------------------------------------------------------
extern "C" void kernel_launch(void* const* d_in, const int* in_sizes, int n_in,
                              void* d_out, int out_size) {
    const float* x  = nullptr;
    const int*   ei = nullptr;
    const float* W1 = nullptr;
    const float* b1 = nullptr;
    const float* W2 = nullptr;
    const float* b2 = nullptr;

    for (int i = 0; i < n_in; i++) {
        switch (in_sizes[i]) {
            case N_NODES * F0:  x  = (const float*)d_in[i]; break;
            case 2 * N_EDGES:   ei = (const int*)  d_in[i]; break;
            case F0 * F1:       W1 = (const float*)d_in[i]; break;
            case F1:            b1 = (const float*)d_in[i]; break;
            case F1 * F2:       W2 = (const float*)d_in[i]; break;
            case F2:            b2 = (const float*)d_in[i]; break;
            default: break;
        }
    }

    float* out = (float*)d_out;
    const int N = N_NODES;
    const int E = N_EDGES;
    const int* src = ei;
    const int* dst = ei + E;

    float *h1s, *r1, *h2s, *dinv;
    int *cnt, *row, *cur, *csr;
    cudaGetSymbolAddress((void**)&h1s, g_h1s);
    cudaGetSymbolAddress((void**)&r1,  g_r1);
    cudaGetSymbolAddress((void**)&h2s, g_h2s);
    cudaGetSymbolAddress((void**)&dinv, g_dinv);
    cudaGetSymbolAddress((void**)&cnt, g_cnt);
    cudaGetSymbolAddress((void**)&row, g_row);
    cudaGetSymbolAddress((void**)&cur, g_cur);
    cudaGetSymbolAddress((void**)&csr, g_csr);

    const int T = 256;

    // 1) degree histogram -> dinv, CSR row offsets + fill
    k_zero_cnt<<<(N + T - 1) / T, T>>>(cnt, N);
    k_count<<<(E + T - 1) / T, T>>>(dst, E, cnt);
    k_dinv<<<(N + T - 1) / T, T>>>(cnt, dinv, N);
    k_scan<<<1, 1024>>>(cnt, row, cur, N, E);
    k_fill<<<(E + T - 1) / T, T>>>(src, dst, E, cur, csr);

    // 2) GEMM1: h1s = (x @ W1) * dinv[row]
    {
        dim3 grid(F1 / 128, (N + 127) / 128);
        k_sgemm<128, 128, 16, 8, 8><<<grid, 256>>>(x, W1, h1s, dinv, N, F1, F0);
    }

    // 3) layer-1 aggregate + bias + relu  -> r1
    {
        int blocks = (N * 32 + T - 1) / T;
        k_agg_csr<4, true><<<blocks, T>>>(h1s, row, csr, dinv, b1, r1, N);
    }

    // 4) GEMM2: h2s = (r1 @ W2) * dinv[row]
    {
        dim3 grid(F2 / 64, (N + 127) / 128);
        k_sgemm<128, 64, 16, 8, 4><<<grid, 256>>>(r1, W2, h2s, dinv, N, F2, F1);
    }

    // 5) layer-2 aggregate + bias -> out
    {
        int blocks = (N * 32 + T - 1) / T;
        k_agg_csr<2, false><<<blocks, T>>>(h2s, row, csr, dinv, b2, out, N);
    }
}

// round 14
// speedup vs baseline: 2.1821x; 1.1572x over previous
#include <cuda_runtime.h>
#include <cuda_bf16.h>
#include <cstdint>

// ---------------------------------------------------------------------------
// GCN 2-layer: out = A_norm( relu( A_norm(x W1) + b1 ) W2 ) + b2
// A_norm = D^-1/2 (A+I) D^-1/2.  Strategy:
//   - GEMM epilogue prescales rows by dinv  ->  hs = (X W) * dinv[row]
//   - CSR-by-dst gather:  out[n] = dinv[n]*(sum_{s in N(n)} hs[s] + hs[n]) + b
//   - bias/relu fused into the aggregation epilogue
//   - GEMM inner loop uses packed fma.rn.f32x2 (Blackwell dual-rate FP32)
//   - device-wide 3-phase scan for CSR row offsets (was: 1-block, 70us)
// edge_index is INT32 on device (JAX x64 disabled).
// ---------------------------------------------------------------------------

#define N_NODES 50000
#define N_EDGES 1600000
#define F0 512
#define F1 128
#define F2 64

#define SCAN_T 256
#define SCAN_BLOCKS ((N_NODES + SCAN_T - 1) / SCAN_T)   // 196

// Scratch (allocation-free rules: device globals)
__device__ float g_h1s [(size_t)N_NODES * F1];   // (x@W1)*dinv
__device__ float g_r1  [(size_t)N_NODES * F1];   // relu(agg1+b1)
__device__ float g_h2s [(size_t)N_NODES * F2];   // (r1@W2)*dinv
__device__ float g_dinv[N_NODES];
__device__ int   g_cnt [N_NODES];
__device__ int   g_row [N_NODES + 1];
__device__ int   g_cur [N_NODES];
__device__ int   g_csr [N_EDGES];
__device__ int   g_bsum[SCAN_BLOCKS];            // per-block sums
__device__ int   g_boff[SCAN_BLOCKS];            // exclusive block offsets

// ---------------------------------------------------------------------------
// f32x2 packed-FMA helpers
// ---------------------------------------------------------------------------
__device__ __forceinline__ unsigned long long pack2(float lo, float hi) {
    unsigned long long r;
    asm("mov.b64 %0, {%1, %2};" : "=l"(r) : "f"(lo), "f"(hi));
    return r;
}
__device__ __forceinline__ void fma2(unsigned long long& d, unsigned long long a,
                                     unsigned long long b) {
    asm("fma.rn.f32x2 %0, %1, %2, %3;" : "=l"(d) : "l"(a), "l"(b), "l"(d));
}
__device__ __forceinline__ float2 unpack2(unsigned long long v) {
    float2 f;
    asm("mov.b64 {%0, %1}, %2;" : "=f"(f.x), "=f"(f.y) : "l"(v));
    return f;
}

// ---------------------------------------------------------------------------
// Degree / CSR build
// ---------------------------------------------------------------------------
__global__ void k_zero_cnt(int* cnt, int n) {
    int i = blockIdx.x * blockDim.x + threadIdx.x;
    if (i < n) cnt[i] = 0;
}
__global__ void k_count(const int* __restrict__ dst, int E, int* cnt) {
    int e = blockIdx.x * blockDim.x + threadIdx.x;
    if (e < E) atomicAdd(&cnt[dst[e]], 1);
}
__global__ void k_dinv(const int* __restrict__ cnt, float* __restrict__ dinv, int n) {
    int i = blockIdx.x * blockDim.x + threadIdx.x;
    if (i < n) dinv[i] = rsqrtf((float)(cnt[i] + 1));  // +1 self-loop
}

// ---- 3-phase device-wide exclusive scan over cnt[0..n) ----
// Phase 1: per-block sums
__global__ void k_scan_bsum(const int* __restrict__ cnt, int* __restrict__ bsum, int n) {
    __shared__ int wsum[32];
    int i = blockIdx.x * SCAN_T + threadIdx.x;
    int v = (i < n) ? cnt[i] : 0;
    // warp reduce
#pragma unroll
    for (int o = 16; o > 0; o >>= 1) v += __shfl_down_sync(0xffffffffu, v, o);
    int lane = threadIdx.x & 31, wid = threadIdx.x >> 5;
    if (lane == 0) wsum[wid] = v;
    __syncthreads();
    if (wid == 0) {
        int w = (lane < SCAN_T / 32) ? wsum[lane] : 0;
#pragma unroll
        for (int o = 16; o > 0; o >>= 1) w += __shfl_down_sync(0xffffffffu, w, o);
        if (lane == 0) bsum[blockIdx.x] = w;
    }
}

// Phase 2: one block scans the block sums (exclusive); also writes row[n]=total
__global__ void k_scan_boff(const int* __restrict__ bsum, int* __restrict__ boff,
                            int nblocks, int* __restrict__ row_n, int total) {
    __shared__ int wsum[32];
    int tid = threadIdx.x;              // SCAN_T threads, SCAN_T >= nblocks
    int v = (tid < nblocks) ? bsum[tid] : 0;
    int lane = tid & 31, wid = tid >> 5;
    int s = v;
#pragma unroll
    for (int o = 1; o < 32; o <<= 1) {
        int t = __shfl_up_sync(0xffffffffu, s, o);
        if (lane >= o) s += t;
    }
    if (lane == 31) wsum[wid] = s;
    __syncthreads();
    if (wid == 0) {
        int w = (lane < SCAN_T / 32) ? wsum[lane] : 0;
#pragma unroll
        for (int o = 1; o < 32; o <<= 1) {
            int t = __shfl_up_sync(0xffffffffu, w, o);
            if (lane >= o) w += t;
        }
        wsum[lane] = w;
    }
    __syncthreads();
    int excl = (s - v) + (wid ? wsum[wid - 1] : 0);
    if (tid < nblocks) boff[tid] = excl;
    if (tid == 0) *row_n = total;       // row_start[n] = E
}

// Phase 3: block-local exclusive scan + block offset -> row_start & cursor
__global__ void k_scan_final(const int* __restrict__ cnt, const int* __restrict__ boff,
                             int* __restrict__ row_start, int* __restrict__ cursor, int n) {
    __shared__ int wsum[32];            // FIXED: was [SCAN_T/32]=8, warp0 writes 32 -> smem OOB
    int i = blockIdx.x * SCAN_T + threadIdx.x;
    int v = (i < n) ? cnt[i] : 0;
    int lane = threadIdx.x & 31, wid = threadIdx.x >> 5;
    int s = v;
#pragma unroll
    for (int o = 1; o < 32; o <<= 1) {
        int t = __shfl_up_sync(0xffffffffu, s, o);
        if (lane >= o) s += t;
    }
    if (lane == 31) wsum[wid] = s;
    __syncthreads();
    if (wid == 0) {
        int w = (lane < SCAN_T / 32) ? wsum[lane] : 0;
#pragma unroll
        for (int o = 1; o < 32; o <<= 1) {
            int t = __shfl_up_sync(0xffffffffu, w, o);
            if (lane >= o) w += t;
        }
        wsum[lane] = w;
    }
    __syncthreads();
    int excl = (s - v) + (wid ? wsum[wid - 1] : 0) + boff[blockIdx.x];
    if (i < n) {
        row_start[i] = excl;
        cursor[i]    = excl;
    }
}

__global__ void k_fill(const int* __restrict__ src, const int* __restrict__ dst,
                       int E, int* __restrict__ cursor, int* __restrict__ csr) {
    int e = blockIdx.x * blockDim.x + threadIdx.x;
    if (e >= E) return;
    int d = dst[e];
    int pos = atomicAdd(&cursor[d], 1);
    csr[pos] = src[e];
}

// ---------------------------------------------------------------------------
// Register-tiled SGEMM with f32x2 packed FMA and row-scale epilogue:
//   C[r, c] = (A[r,:] @ B[:,c]) * rowscale[r]
// ---------------------------------------------------------------------------
template <int BM, int BN, int BK, int TM, int TN>
__global__ void k_sgemm(const float* __restrict__ A, const float* __restrict__ B,
                        float* __restrict__ C, const float* __restrict__ rowscale,
                        int M, int N, int K) {
    __shared__ float As[BK][BM];
    __shared__ float Bs[BK][BN];
    constexpr int THREADS = (BM / TM) * (BN / TN);
    constexpr int TN2 = TN / 2;

    const int tid = threadIdx.x;
    const int tx  = tid % (BN / TN);
    const int ty  = tid / (BN / TN);
    const int rowBase = blockIdx.y * BM;
    const int colBase = blockIdx.x * BN;

    unsigned long long acc2[TM][TN2];
#pragma unroll
    for (int i = 0; i < TM; i++)
#pragma unroll
        for (int j = 0; j < TN2; j++) acc2[i][j] = 0ull;

    for (int k0 = 0; k0 < K; k0 += BK) {
#pragma unroll
        for (int idx = tid; idx < BM * BK / 4; idx += THREADS) {
            int r  = idx / (BK / 4);
            int c4 = idx % (BK / 4);
            float4 v = make_float4(0.f, 0.f, 0.f, 0.f);
            int gr = rowBase + r;
            if (gr < M)
                v = *reinterpret_cast<const float4*>(&A[(size_t)gr * K + k0 + c4 * 4]);
            As[c4 * 4 + 0][r] = v.x;
            As[c4 * 4 + 1][r] = v.y;
            As[c4 * 4 + 2][r] = v.z;
            As[c4 * 4 + 3][r] = v.w;
        }
#pragma unroll
        for (int idx = tid; idx < BK * BN / 4; idx += THREADS) {
            int r  = idx / (BN / 4);
            int c4 = idx % (BN / 4);
            *reinterpret_cast<float4*>(&Bs[r][c4 * 4]) =
                *reinterpret_cast<const float4*>(&B[(size_t)(k0 + r) * N + colBase + c4 * 4]);
        }
        __syncthreads();

#pragma unroll
        for (int k = 0; k < BK; k++) {
            float ra[TM];
            unsigned long long rb2[TN2];
#pragma unroll
            for (int i = 0; i < TM; i++) ra[i] = As[k][ty * TM + i];
            const unsigned long long* bp =
                reinterpret_cast<const unsigned long long*>(&Bs[k][tx * TN]);
#pragma unroll
            for (int j = 0; j < TN2; j++) rb2[j] = bp[j];
#pragma unroll
            for (int i = 0; i < TM; i++) {
                unsigned long long a2 = pack2(ra[i], ra[i]);
#pragma unroll
                for (int j = 0; j < TN2; j++) fma2(acc2[i][j], a2, rb2[j]);
            }
        }
        __syncthreads();
    }

#pragma unroll
    for (int i = 0; i < TM; i++) {
        int gr = rowBase + ty * TM + i;
        if (gr >= M) continue;
        float sc = rowscale ? rowscale[gr] : 1.0f;
#pragma unroll
        for (int j = 0; j < TN2; j += 2) {
            float2 a = unpack2(acc2[i][j]);
            float2 b = unpack2(acc2[i][j + 1]);
            float4 v = make_float4(a.x * sc, a.y * sc, b.x * sc, b.y * sc);
            *reinterpret_cast<float4*>(&C[(size_t)gr * N + colBase + tx * TN + j * 2]) = v;
        }
    }
}

// ---------------------------------------------------------------------------
// CSR gather-aggregate: one warp per node, VEC floats per lane (F = 32*VEC)
//   out[n] = dinv[n] * ( sum_{e} hs[csr[e]] + hs[n] ) + bias   [relu]
// ---------------------------------------------------------------------------
template <int VEC, bool RELU>
__global__ void k_agg_csr(const float* __restrict__ hs, const int* __restrict__ row_start,
                          const int* __restrict__ csr, const float* __restrict__ dinv,
                          const float* __restrict__ bias, float* __restrict__ out, int n) {
    constexpr int F = 32 * VEC;
    int warp = (blockIdx.x * blockDim.x + threadIdx.x) >> 5;
    int lane = threadIdx.x & 31;
    if (warp >= n) return;

    int e0 = row_start[warp];
    int e1 = row_start[warp + 1];

    float acc[VEC];
    // self term
    if (VEC == 4) {
        float4 v = *reinterpret_cast<const float4*>(hs + (size_t)warp * F + lane * 4);
        acc[0] = v.x; acc[1] = v.y; acc[2] = v.z; acc[3] = v.w;
    } else {
        float2 v = *reinterpret_cast<const float2*>(hs + (size_t)warp * F + lane * 2);
        acc[0] = v.x; acc[1] = v.y;
    }

    int e = e0;
    for (; e + 4 <= e1; e += 4) {
        int s0 = csr[e], s1 = csr[e + 1], s2 = csr[e + 2], s3 = csr[e + 3];
        if (VEC == 4) {
            float4 v0 = *reinterpret_cast<const float4*>(hs + (size_t)s0 * F + lane * 4);
            float4 v1 = *reinterpret_cast<const float4*>(hs + (size_t)s1 * F + lane * 4);
            float4 v2 = *reinterpret_cast<const float4*>(hs + (size_t)s2 * F + lane * 4);
            float4 v3 = *reinterpret_cast<const float4*>(hs + (size_t)s3 * F + lane * 4);
            acc[0] += v0.x + v1.x + v2.x + v3.x;
            acc[1] += v0.y + v1.y + v2.y + v3.y;
            acc[2] += v0.z + v1.z + v2.z + v3.z;
            acc[3] += v0.w + v1.w + v2.w + v3.w;
        } else {
            float2 v0 = *reinterpret_cast<const float2*>(hs + (size_t)s0 * F + lane * 2);
            float2 v1 = *reinterpret_cast<const float2*>(hs + (size_t)s1 * F + lane * 2);
            float2 v2 = *reinterpret_cast<const float2*>(hs + (size_t)s2 * F + lane * 2);
            float2 v3 = *reinterpret_cast<const float2*>(hs + (size_t)s3 * F + lane * 2);
            acc[0] += v0.x + v1.x + v2.x + v3.x;
            acc[1] += v0.y + v1.y + v2.y + v3.y;
        }
    }
    for (; e < e1; e++) {
        int s = csr[e];
        if (VEC == 4) {
            float4 v = *reinterpret_cast<const float4*>(hs + (size_t)s * F + lane * 4);
            acc[0] += v.x; acc[1] += v.y; acc[2] += v.z; acc[3] += v.w;
        } else {
            float2 v = *reinterpret_cast<const float2*>(hs + (size_t)s * F + lane * 2);
            acc[0] += v.x; acc[1] += v.y;
        }
    }

    float dn = dinv[warp];
    float* op = out + (size_t)warp * F + lane * VEC;
    if (VEC == 4) {
        float4 bsv = *reinterpret_cast<const float4*>(bias + lane * 4);
        float4 r = make_float4(acc[0] * dn + bsv.x, acc[1] * dn + bsv.y,
                               acc[2] * dn + bsv.z, acc[3] * dn + bsv.w);
        if (RELU) {
            r.x = fmaxf(r.x, 0.f); r.y = fmaxf(r.y, 0.f);
            r.z = fmaxf(r.z, 0.f); r.w = fmaxf(r.w, 0.f);
        }
        *reinterpret_cast<float4*>(op) = r;
    } else {
        float2 bsv = *reinterpret_cast<const float2*>(bias + lane * 2);
        float2 r = make_float2(acc[0] * dn + bsv.x, acc[1] * dn + bsv.y);
        if (RELU) { r.x = fmaxf(r.x, 0.f); r.y = fmaxf(r.y, 0.f); }
        *reinterpret_cast<float2*>(op) = r;
    }
}

// ---------------------------------------------------------------------------
// Launcher — bind inputs BY ELEMENT COUNT
// ---------------------------------------------------------------------------
extern "C" void kernel_launch(void* const* d_in, const int* in_sizes, int n_in,
                              void* d_out, int out_size) {
    const float* x  = nullptr;
    const int*   ei = nullptr;
    const float* W1 = nullptr;
    const float* b1 = nullptr;
    const float* W2 = nullptr;
    const float* b2 = nullptr;

    for (int i = 0; i < n_in; i++) {
        switch (in_sizes[i]) {
            case N_NODES * F0:  x  = (const float*)d_in[i]; break;
            case 2 * N_EDGES:   ei = (const int*)  d_in[i]; break;
            case F0 * F1:       W1 = (const float*)d_in[i]; break;
            case F1:            b1 = (const float*)d_in[i]; break;
            case F1 * F2:       W2 = (const float*)d_in[i]; break;
            case F2:            b2 = (const float*)d_in[i]; break;
            default: break;
        }
    }

    float* out = (float*)d_out;
    const int N = N_NODES;
    const int E = N_EDGES;
    const int* src = ei;
    const int* dst = ei + E;

    float *h1s, *r1, *h2s, *dinv;
    int *cnt, *row, *cur, *csr, *bsum, *boff;
    cudaGetSymbolAddress((void**)&h1s, g_h1s);
    cudaGetSymbolAddress((void**)&r1,  g_r1);
    cudaGetSymbolAddress((void**)&h2s, g_h2s);
    cudaGetSymbolAddress((void**)&dinv, g_dinv);
    cudaGetSymbolAddress((void**)&cnt, g_cnt);
    cudaGetSymbolAddress((void**)&row, g_row);
    cudaGetSymbolAddress((void**)&cur, g_cur);
    cudaGetSymbolAddress((void**)&csr, g_csr);
    cudaGetSymbolAddress((void**)&bsum, g_bsum);
    cudaGetSymbolAddress((void**)&boff, g_boff);

    const int T = 256;

    // 1) degree histogram -> dinv, CSR row offsets (3-phase scan) + fill
    k_zero_cnt<<<(N + T - 1) / T, T>>>(cnt, N);
    k_count<<<(E + T - 1) / T, T>>>(dst, E, cnt);
    k_dinv<<<(N + T - 1) / T, T>>>(cnt, dinv, N);
    k_scan_bsum<<<SCAN_BLOCKS, SCAN_T>>>(cnt, bsum, N);
    k_scan_boff<<<1, SCAN_T>>>(bsum, boff, SCAN_BLOCKS, &row[N], E);
    k_scan_final<<<SCAN_BLOCKS, SCAN_T>>>(cnt, boff, row, cur, N);
    k_fill<<<(E + T - 1) / T, T>>>(src, dst, E, cur, csr);

    // 2) GEMM1: h1s = (x @ W1) * dinv[row]
    {
        dim3 grid(F1 / 128, (N + 127) / 128);
        k_sgemm<128, 128, 16, 8, 8><<<grid, 256>>>(x, W1, h1s, dinv, N, F1, F0);
    }

    // 3) layer-1 aggregate + bias + relu  -> r1
    {
        int blocks = (N * 32 + T - 1) / T;
        k_agg_csr<4, true><<<blocks, T>>>(h1s, row, csr, dinv, b1, r1, N);
    }

    // 4) GEMM2: h2s = (r1 @ W2) * dinv[row]
    {
        dim3 grid(F2 / 64, (N + 127) / 128);
        k_sgemm<128, 64, 16, 8, 4><<<grid, 256>>>(r1, W2, h2s, dinv, N, F2, F1);
    }

    // 5) layer-2 aggregate + bias -> out
    {
        int blocks = (N * 32 + T - 1) / T;
        k_agg_csr<2, false><<<blocks, T>>>(h2s, row, csr, dinv, b2, out, N);
    }
}

// round 15
// speedup vs baseline: 2.8815x; 1.3205x over previous
#include <cuda_runtime.h>
#include <cuda_bf16.h>
#include <cstdint>

// ---------------------------------------------------------------------------
// GCN 2-layer: out = A_norm( relu( A_norm(x W1) + b1 ) W2 ) + b2
// A_norm = D^-1/2 (A+I) D^-1/2.
//   - GEMM1 (50000x512x128): tf32 mma.sync tensor-core GEMM, rowscale epilogue
//   - GEMM2 (50000x128x64):  f32x2 SIMT GEMM (small; keeps fp32 precision)
//   - CSR-by-dst gather aggregation, bias/relu fused
//   - 3-phase device-wide scan for CSR row offsets
// edge_index is INT32 on device (JAX x64 disabled).
// ---------------------------------------------------------------------------

#define N_NODES 50000
#define N_EDGES 1600000
#define F0 512
#define F1 128
#define F2 64

#define SCAN_T 256
#define SCAN_BLOCKS ((N_NODES + SCAN_T - 1) / SCAN_T)   // 196

// Scratch (allocation-free rules: device globals)
__device__ float g_h1s [(size_t)N_NODES * F1];   // (x@W1)*dinv
__device__ float g_r1  [(size_t)N_NODES * F1];   // relu(agg1+b1)
__device__ float g_h2s [(size_t)N_NODES * F2];   // (r1@W2)*dinv
__device__ float g_dinv[N_NODES];
__device__ int   g_cnt [N_NODES];
__device__ int   g_row [N_NODES + 1];
__device__ int   g_cur [N_NODES];
__device__ int   g_csr [N_EDGES];
__device__ int   g_bsum[SCAN_BLOCKS];
__device__ int   g_boff[SCAN_BLOCKS];

// ---------------------------------------------------------------------------
// f32x2 packed-FMA helpers
// ---------------------------------------------------------------------------
__device__ __forceinline__ unsigned long long pack2(float lo, float hi) {
    unsigned long long r;
    asm("mov.b64 %0, {%1, %2};" : "=l"(r) : "f"(lo), "f"(hi));
    return r;
}
__device__ __forceinline__ void fma2(unsigned long long& d, unsigned long long a,
                                     unsigned long long b) {
    asm("fma.rn.f32x2 %0, %1, %2, %3;" : "=l"(d) : "l"(a), "l"(b), "l"(d));
}
__device__ __forceinline__ float2 unpack2(unsigned long long v) {
    float2 f;
    asm("mov.b64 {%0, %1}, %2;" : "=f"(f.x), "=f"(f.y) : "l"(v));
    return f;
}
__device__ __forceinline__ uint32_t f2tf32(float f) {
    uint32_t r;
    asm("cvt.rna.tf32.f32 %0, %1;" : "=r"(r) : "f"(f));
    return r;
}

// ---------------------------------------------------------------------------
// Degree / CSR build
// ---------------------------------------------------------------------------
__global__ void k_zero_cnt(int* cnt, int n) {
    int i = blockIdx.x * blockDim.x + threadIdx.x;
    if (i < n) cnt[i] = 0;
}
__global__ void k_count(const int* __restrict__ dst, int E, int* cnt) {
    int e = blockIdx.x * blockDim.x + threadIdx.x;
    if (e < E) atomicAdd(&cnt[dst[e]], 1);
}
__global__ void k_dinv(const int* __restrict__ cnt, float* __restrict__ dinv, int n) {
    int i = blockIdx.x * blockDim.x + threadIdx.x;
    if (i < n) dinv[i] = rsqrtf((float)(cnt[i] + 1));  // +1 self-loop
}

// ---- 3-phase device-wide exclusive scan over cnt[0..n) ----
__global__ void k_scan_bsum(const int* __restrict__ cnt, int* __restrict__ bsum, int n) {
    __shared__ int wsum[32];
    int i = blockIdx.x * SCAN_T + threadIdx.x;
    int v = (i < n) ? cnt[i] : 0;
#pragma unroll
    for (int o = 16; o > 0; o >>= 1) v += __shfl_down_sync(0xffffffffu, v, o);
    int lane = threadIdx.x & 31, wid = threadIdx.x >> 5;
    if (lane == 0) wsum[wid] = v;
    __syncthreads();
    if (wid == 0) {
        int w = (lane < SCAN_T / 32) ? wsum[lane] : 0;
#pragma unroll
        for (int o = 16; o > 0; o >>= 1) w += __shfl_down_sync(0xffffffffu, w, o);
        if (lane == 0) bsum[blockIdx.x] = w;
    }
}

__global__ void k_scan_boff(const int* __restrict__ bsum, int* __restrict__ boff,
                            int nblocks, int* __restrict__ row_n, int total) {
    __shared__ int wsum[32];
    int tid = threadIdx.x;
    int v = (tid < nblocks) ? bsum[tid] : 0;
    int lane = tid & 31, wid = tid >> 5;
    int s = v;
#pragma unroll
    for (int o = 1; o < 32; o <<= 1) {
        int t = __shfl_up_sync(0xffffffffu, s, o);
        if (lane >= o) s += t;
    }
    if (lane == 31) wsum[wid] = s;
    __syncthreads();
    if (wid == 0) {
        int w = (lane < SCAN_T / 32) ? wsum[lane] : 0;
#pragma unroll
        for (int o = 1; o < 32; o <<= 1) {
            int t = __shfl_up_sync(0xffffffffu, w, o);
            if (lane >= o) w += t;
        }
        wsum[lane] = w;
    }
    __syncthreads();
    int excl = (s - v) + (wid ? wsum[wid - 1] : 0);
    if (tid < nblocks) boff[tid] = excl;
    if (tid == 0) *row_n = total;
}

__global__ void k_scan_final(const int* __restrict__ cnt, const int* __restrict__ boff,
                             int* __restrict__ row_start, int* __restrict__ cursor, int n) {
    __shared__ int wsum[32];
    int i = blockIdx.x * SCAN_T + threadIdx.x;
    int v = (i < n) ? cnt[i] : 0;
    int lane = threadIdx.x & 31, wid = threadIdx.x >> 5;
    int s = v;
#pragma unroll
    for (int o = 1; o < 32; o <<= 1) {
        int t = __shfl_up_sync(0xffffffffu, s, o);
        if (lane >= o) s += t;
    }
    if (lane == 31) wsum[wid] = s;
    __syncthreads();
    if (wid == 0) {
        int w = (lane < SCAN_T / 32) ? wsum[lane] : 0;
#pragma unroll
        for (int o = 1; o < 32; o <<= 1) {
            int t = __shfl_up_sync(0xffffffffu, w, o);
            if (lane >= o) w += t;
        }
        wsum[lane] = w;
    }
    __syncthreads();
    int excl = (s - v) + (wid ? wsum[wid - 1] : 0) + boff[blockIdx.x];
    if (i < n) {
        row_start[i] = excl;
        cursor[i]    = excl;
    }
}

__global__ void k_fill(const int* __restrict__ src, const int* __restrict__ dst,
                       int E, int* __restrict__ cursor, int* __restrict__ csr) {
    int e = blockIdx.x * blockDim.x + threadIdx.x;
    if (e >= E) return;
    int d = dst[e];
    int pos = atomicAdd(&cursor[d], 1);
    csr[pos] = src[e];
}

// ---------------------------------------------------------------------------
// GEMM1: tf32 tensor-core GEMM.  C[M,128] = (A[M,512] @ B[512,128]) * scale[r]
// Block: 128x128x32 tile, 256 threads (8 warps as 4x2). Warp: 32x64 via
// 2x8 m16n8k8 mma tiles.
// ---------------------------------------------------------------------------
#define G1_BM 128
#define G1_BN 128
#define G1_BK 32
#define G1_APAD 4
#define G1_BPAD 4

__global__ void __launch_bounds__(256)
k_gemm1_tf32(const float* __restrict__ A, const float* __restrict__ B,
             float* __restrict__ C, const float* __restrict__ rowscale, int M) {
    __shared__ float As[G1_BM][G1_BK + G1_APAD];   // stride 36: frag loads conflict-free
    __shared__ float Bs[G1_BK][G1_BN + G1_BPAD];   // stride 132: 2-way worst case

    const int tid  = threadIdx.x;
    const int lane = tid & 31;
    const int wid  = tid >> 5;
    const int wrow = wid & 3;          // 0..3  -> 32-row slice
    const int wcol = wid >> 2;         // 0..1  -> 64-col slice
    const int rowBase = blockIdx.x * G1_BM;

    float c[2][8][4];                  // [mi][ni][frag]
#pragma unroll
    for (int mi = 0; mi < 2; mi++)
#pragma unroll
        for (int ni = 0; ni < 8; ni++)
#pragma unroll
            for (int r = 0; r < 4; r++) c[mi][ni][r] = 0.0f;

    const int lq = lane >> 2;          // lane/4 : 0..7
    const int lr = lane & 3;           // lane%4 : 0..3

    for (int k0 = 0; k0 < F0; k0 += G1_BK) {
        // Load A tile 128x32 (float4, 4 per thread)
#pragma unroll
        for (int it = 0; it < 4; it++) {
            int idx = tid + it * 256;          // 0..1023
            int r  = idx >> 3;                 // /8  (32/4=8 float4 per row)
            int c4 = idx & 7;
            float4 v = make_float4(0.f, 0.f, 0.f, 0.f);
            int gr = rowBase + r;
            if (gr < M)
                v = *reinterpret_cast<const float4*>(&A[(size_t)gr * F0 + k0 + c4 * 4]);
            As[r][c4 * 4 + 0] = v.x;
            As[r][c4 * 4 + 1] = v.y;
            As[r][c4 * 4 + 2] = v.z;
            As[r][c4 * 4 + 3] = v.w;
        }
        // Load B tile 32x128 (float4, 4 per thread)
#pragma unroll
        for (int it = 0; it < 4; it++) {
            int idx = tid + it * 256;
            int r  = idx >> 5;                 // /32 (128/4=32 float4 per row)
            int c4 = idx & 31;
            float4 v = *reinterpret_cast<const float4*>(&B[(size_t)(k0 + r) * F1 + c4 * 4]);
            Bs[r][c4 * 4 + 0] = v.x;
            Bs[r][c4 * 4 + 1] = v.y;
            Bs[r][c4 * 4 + 2] = v.z;
            Bs[r][c4 * 4 + 3] = v.w;
        }
        __syncthreads();

#pragma unroll
        for (int kk = 0; kk < G1_BK; kk += 8) {
            // A fragments: 2 m16 tiles
            uint32_t a[2][4];
#pragma unroll
            for (int mi = 0; mi < 2; mi++) {
                int rb = wrow * 32 + mi * 16;
                a[mi][0] = f2tf32(As[rb + lq    ][kk + lr    ]);
                a[mi][1] = f2tf32(As[rb + lq + 8][kk + lr    ]);
                a[mi][2] = f2tf32(As[rb + lq    ][kk + lr + 4]);
                a[mi][3] = f2tf32(As[rb + lq + 8][kk + lr + 4]);
            }
            // B fragments: 8 n8 tiles
            uint32_t b[8][2];
#pragma unroll
            for (int ni = 0; ni < 8; ni++) {
                int cb = wcol * 64 + ni * 8;
                b[ni][0] = f2tf32(Bs[kk + lr    ][cb + lq]);
                b[ni][1] = f2tf32(Bs[kk + lr + 4][cb + lq]);
            }
#pragma unroll
            for (int mi = 0; mi < 2; mi++)
#pragma unroll
                for (int ni = 0; ni < 8; ni++) {
                    asm volatile(
                        "mma.sync.aligned.m16n8k8.row.col.f32.tf32.tf32.f32 "
                        "{%0,%1,%2,%3}, {%4,%5,%6,%7}, {%8,%9}, {%0,%1,%2,%3};"
                        : "+f"(c[mi][ni][0]), "+f"(c[mi][ni][1]),
                          "+f"(c[mi][ni][2]), "+f"(c[mi][ni][3])
                        : "r"(a[mi][0]), "r"(a[mi][1]), "r"(a[mi][2]), "r"(a[mi][3]),
                          "r"(b[ni][0]), "r"(b[ni][1]));
                }
        }
        __syncthreads();
    }

    // Epilogue: C[row][col] layout per m16n8 fragment:
    //   c0,c1: row = rb + lane/4,   cols = cb + (lane%4)*2 + {0,1}
    //   c2,c3: row = rb + lane/4+8, same cols
#pragma unroll
    for (int mi = 0; mi < 2; mi++) {
        int rb = rowBase + wrow * 32 + mi * 16;
        int r0 = rb + lq;
        int r1 = rb + lq + 8;
        float s0 = (r0 < M) ? rowscale[r0] : 0.0f;
        float s1 = (r1 < M) ? rowscale[r1] : 0.0f;
#pragma unroll
        for (int ni = 0; ni < 8; ni++) {
            int cb = wcol * 64 + ni * 8 + lr * 2;
            if (r0 < M) {
                float2 v0 = make_float2(c[mi][ni][0] * s0, c[mi][ni][1] * s0);
                *reinterpret_cast<float2*>(&C[(size_t)r0 * F1 + cb]) = v0;
            }
            if (r1 < M) {
                float2 v1 = make_float2(c[mi][ni][2] * s1, c[mi][ni][3] * s1);
                *reinterpret_cast<float2*>(&C[(size_t)r1 * F1 + cb]) = v1;
            }
        }
    }
}

// ---------------------------------------------------------------------------
// SIMT SGEMM (f32x2) with row-scale epilogue — used for GEMM2
// ---------------------------------------------------------------------------
template <int BM, int BN, int BK, int TM, int TN>
__global__ void k_sgemm(const float* __restrict__ A, const float* __restrict__ B,
                        float* __restrict__ C, const float* __restrict__ rowscale,
                        int M, int N, int K) {
    __shared__ float As[BK][BM];
    __shared__ float Bs[BK][BN];
    constexpr int THREADS = (BM / TM) * (BN / TN);
    constexpr int TN2 = TN / 2;

    const int tid = threadIdx.x;
    const int tx  = tid % (BN / TN);
    const int ty  = tid / (BN / TN);
    const int rowBase = blockIdx.y * BM;
    const int colBase = blockIdx.x * BN;

    unsigned long long acc2[TM][TN2];
#pragma unroll
    for (int i = 0; i < TM; i++)
#pragma unroll
        for (int j = 0; j < TN2; j++) acc2[i][j] = 0ull;

    for (int k0 = 0; k0 < K; k0 += BK) {
#pragma unroll
        for (int idx = tid; idx < BM * BK / 4; idx += THREADS) {
            int r  = idx / (BK / 4);
            int c4 = idx % (BK / 4);
            float4 v = make_float4(0.f, 0.f, 0.f, 0.f);
            int gr = rowBase + r;
            if (gr < M)
                v = *reinterpret_cast<const float4*>(&A[(size_t)gr * K + k0 + c4 * 4]);
            As[c4 * 4 + 0][r] = v.x;
            As[c4 * 4 + 1][r] = v.y;
            As[c4 * 4 + 2][r] = v.z;
            As[c4 * 4 + 3][r] = v.w;
        }
#pragma unroll
        for (int idx = tid; idx < BK * BN / 4; idx += THREADS) {
            int r  = idx / (BN / 4);
            int c4 = idx % (BN / 4);
            *reinterpret_cast<float4*>(&Bs[r][c4 * 4]) =
                *reinterpret_cast<const float4*>(&B[(size_t)(k0 + r) * N + colBase + c4 * 4]);
        }
        __syncthreads();

#pragma unroll
        for (int k = 0; k < BK; k++) {
            float ra[TM];
            unsigned long long rb2[TN2];
#pragma unroll
            for (int i = 0; i < TM; i++) ra[i] = As[k][ty * TM + i];
            const unsigned long long* bp =
                reinterpret_cast<const unsigned long long*>(&Bs[k][tx * TN]);
#pragma unroll
            for (int j = 0; j < TN2; j++) rb2[j] = bp[j];
#pragma unroll
            for (int i = 0; i < TM; i++) {
                unsigned long long a2 = pack2(ra[i], ra[i]);
#pragma unroll
                for (int j = 0; j < TN2; j++) fma2(acc2[i][j], a2, rb2[j]);
            }
        }
        __syncthreads();
    }

#pragma unroll
    for (int i = 0; i < TM; i++) {
        int gr = rowBase + ty * TM + i;
        if (gr >= M) continue;
        float sc = rowscale ? rowscale[gr] : 1.0f;
#pragma unroll
        for (int j = 0; j < TN2; j += 2) {
            float2 a = unpack2(acc2[i][j]);
            float2 b = unpack2(acc2[i][j + 1]);
            float4 v = make_float4(a.x * sc, a.y * sc, b.x * sc, b.y * sc);
            *reinterpret_cast<float4*>(&C[(size_t)gr * N + colBase + tx * TN + j * 2]) = v;
        }
    }
}

// ---------------------------------------------------------------------------
// CSR gather-aggregate: one warp per node, VEC floats per lane (F = 32*VEC)
//   out[n] = dinv[n] * ( sum_{e} hs[csr[e]] + hs[n] ) + bias   [relu]
// ---------------------------------------------------------------------------
template <int VEC, bool RELU>
__global__ void k_agg_csr(const float* __restrict__ hs, const int* __restrict__ row_start,
                          const int* __restrict__ csr, const float* __restrict__ dinv,
                          const float* __restrict__ bias, float* __restrict__ out, int n) {
    constexpr int F = 32 * VEC;
    int warp = (blockIdx.x * blockDim.x + threadIdx.x) >> 5;
    int lane = threadIdx.x & 31;
    if (warp >= n) return;

    int e0 = row_start[warp];
    int e1 = row_start[warp + 1];

    float acc[VEC];
    if (VEC == 4) {
        float4 v = *reinterpret_cast<const float4*>(hs + (size_t)warp * F + lane * 4);
        acc[0] = v.x; acc[1] = v.y; acc[2] = v.z; acc[3] = v.w;
    } else {
        float2 v = *reinterpret_cast<const float2*>(hs + (size_t)warp * F + lane * 2);
        acc[0] = v.x; acc[1] = v.y;
    }

    int e = e0;
    for (; e + 4 <= e1; e += 4) {
        int s0 = csr[e], s1 = csr[e + 1], s2 = csr[e + 2], s3 = csr[e + 3];
        if (VEC == 4) {
            float4 v0 = *reinterpret_cast<const float4*>(hs + (size_t)s0 * F + lane * 4);
            float4 v1 = *reinterpret_cast<const float4*>(hs + (size_t)s1 * F + lane * 4);
            float4 v2 = *reinterpret_cast<const float4*>(hs + (size_t)s2 * F + lane * 4);
            float4 v3 = *reinterpret_cast<const float4*>(hs + (size_t)s3 * F + lane * 4);
            acc[0] += v0.x + v1.x + v2.x + v3.x;
            acc[1] += v0.y + v1.y + v2.y + v3.y;
            acc[2] += v0.z + v1.z + v2.z + v3.z;
            acc[3] += v0.w + v1.w + v2.w + v3.w;
        } else {
            float2 v0 = *reinterpret_cast<const float2*>(hs + (size_t)s0 * F + lane * 2);
            float2 v1 = *reinterpret_cast<const float2*>(hs + (size_t)s1 * F + lane * 2);
            float2 v2 = *reinterpret_cast<const float2*>(hs + (size_t)s2 * F + lane * 2);
            float2 v3 = *reinterpret_cast<const float2*>(hs + (size_t)s3 * F + lane * 2);
            acc[0] += v0.x + v1.x + v2.x + v3.x;
            acc[1] += v0.y + v1.y + v2.y + v3.y;
        }
    }
    for (; e < e1; e++) {
        int s = csr[e];
        if (VEC == 4) {
            float4 v = *reinterpret_cast<const float4*>(hs + (size_t)s * F + lane * 4);
            acc[0] += v.x; acc[1] += v.y; acc[2] += v.z; acc[3] += v.w;
        } else {
            float2 v = *reinterpret_cast<const float2*>(hs + (size_t)s * F + lane * 2);
            acc[0] += v.x; acc[1] += v.y;
        }
    }

    float dn = dinv[warp];
    float* op = out + (size_t)warp * F + lane * VEC;
    if (VEC == 4) {
        float4 bsv = *reinterpret_cast<const float4*>(bias + lane * 4);
        float4 r = make_float4(acc[0] * dn + bsv.x, acc[1] * dn + bsv.y,
                               acc[2] * dn + bsv.z, acc[3] * dn + bsv.w);
        if (RELU) {
            r.x = fmaxf(r.x, 0.f); r.y = fmaxf(r.y, 0.f);
            r.z = fmaxf(r.z, 0.f); r.w = fmaxf(r.w, 0.f);
        }
        *reinterpret_cast<float4*>(op) = r;
    } else {
        float2 bsv = *reinterpret_cast<const float2*>(bias + lane * 2);
        float2 r = make_float2(acc[0] * dn + bsv.x, acc[1] * dn + bsv.y);
        if (RELU) { r.x = fmaxf(r.x, 0.f); r.y = fmaxf(r.y, 0.f); }
        *reinterpret_cast<float2*>(op) = r;
    }
}

// ---------------------------------------------------------------------------
// Launcher — bind inputs BY ELEMENT COUNT
// ---------------------------------------------------------------------------
extern "C" void kernel_launch(void* const* d_in, const int* in_sizes, int n_in,
                              void* d_out, int out_size) {
    const float* x  = nullptr;
    const int*   ei = nullptr;
    const float* W1 = nullptr;
    const float* b1 = nullptr;
    const float* W2 = nullptr;
    const float* b2 = nullptr;

    for (int i = 0; i < n_in; i++) {
        switch (in_sizes[i]) {
            case N_NODES * F0:  x  = (const float*)d_in[i]; break;
            case 2 * N_EDGES:   ei = (const int*)  d_in[i]; break;
            case F0 * F1:       W1 = (const float*)d_in[i]; break;
            case F1:            b1 = (const float*)d_in[i]; break;
            case F1 * F2:       W2 = (const float*)d_in[i]; break;
            case F2:            b2 = (const float*)d_in[i]; break;
            default: break;
        }
    }

    float* out = (float*)d_out;
    const int N = N_NODES;
    const int E = N_EDGES;
    const int* src = ei;
    const int* dst = ei + E;

    float *h1s, *r1, *h2s, *dinv;
    int *cnt, *row, *cur, *csr, *bsum, *boff;
    cudaGetSymbolAddress((void**)&h1s, g_h1s);
    cudaGetSymbolAddress((void**)&r1,  g_r1);
    cudaGetSymbolAddress((void**)&h2s, g_h2s);
    cudaGetSymbolAddress((void**)&dinv, g_dinv);
    cudaGetSymbolAddress((void**)&cnt, g_cnt);
    cudaGetSymbolAddress((void**)&row, g_row);
    cudaGetSymbolAddress((void**)&cur, g_cur);
    cudaGetSymbolAddress((void**)&csr, g_csr);
    cudaGetSymbolAddress((void**)&bsum, g_bsum);
    cudaGetSymbolAddress((void**)&boff, g_boff);

    const int T = 256;

    // 1) degree histogram -> dinv, CSR row offsets (3-phase scan) + fill
    k_zero_cnt<<<(N + T - 1) / T, T>>>(cnt, N);
    k_count<<<(E + T - 1) / T, T>>>(dst, E, cnt);
    k_dinv<<<(N + T - 1) / T, T>>>(cnt, dinv, N);
    k_scan_bsum<<<SCAN_BLOCKS, SCAN_T>>>(cnt, bsum, N);
    k_scan_boff<<<1, SCAN_T>>>(bsum, boff, SCAN_BLOCKS, &row[N], E);
    k_scan_final<<<SCAN_BLOCKS, SCAN_T>>>(cnt, boff, row, cur, N);
    k_fill<<<(E + T - 1) / T, T>>>(src, dst, E, cur, csr);

    // 2) GEMM1 (tf32 tensor cores): h1s = (x @ W1) * dinv[row]
    k_gemm1_tf32<<<(N + G1_BM - 1) / G1_BM, 256>>>(x, W1, h1s, dinv, N);

    // 3) layer-1 aggregate + bias + relu  -> r1
    {
        int blocks = (N * 32 + T - 1) / T;
        k_agg_csr<4, true><<<blocks, T>>>(h1s, row, csr, dinv, b1, r1, N);
    }

    // 4) GEMM2 (f32x2 SIMT): h2s = (r1 @ W2) * dinv[row]
    {
        dim3 grid(F2 / 64, (N + 127) / 128);
        k_sgemm<128, 64, 16, 8, 4><<<grid, 256>>>(r1, W2, h2s, dinv, N, F2, F1);
    }

    // 5) layer-2 aggregate + bias -> out
    {
        int blocks = (N * 32 + T - 1) / T;
        k_agg_csr<2, false><<<blocks, T>>>(h2s, row, csr, dinv, b2, out, N);
    }
}

// round 16
// speedup vs baseline: 4.2004x; 1.4577x over previous
#include <cuda_runtime.h>
#include <cuda_bf16.h>
#include <cstdint>

// ---------------------------------------------------------------------------
// GCN 2-layer: out = A_norm( relu( A_norm(x W1) + b1 ) W2 ) + b2
// A_norm = D^-1/2 (A+I) D^-1/2.
//   - GEMM1 (50000x512x128): tf32 mma.sync, smem pre-converted to tf32
//   - GEMM2 (50000x128x64):  tf32 mma.sync, same scheme
//   - CSR-by-dst gather aggregation, bias/relu fused
//   - 3-phase device-wide scan for CSR row offsets
// edge_index is INT32 on device (JAX x64 disabled).
// ---------------------------------------------------------------------------

#define N_NODES 50000
#define N_EDGES 1600000
#define F0 512
#define F1 128
#define F2 64

#define SCAN_T 256
#define SCAN_BLOCKS ((N_NODES + SCAN_T - 1) / SCAN_T)   // 196

// Scratch (allocation-free rules: device globals)
__device__ float g_h1s [(size_t)N_NODES * F1];   // (x@W1)*dinv
__device__ float g_r1  [(size_t)N_NODES * F1];   // relu(agg1+b1)
__device__ float g_h2s [(size_t)N_NODES * F2];   // (r1@W2)*dinv
__device__ float g_dinv[N_NODES];
__device__ int   g_cnt [N_NODES];
__device__ int   g_row [N_NODES + 1];
__device__ int   g_cur [N_NODES];
__device__ int   g_csr [N_EDGES];
__device__ int   g_bsum[SCAN_BLOCKS];
__device__ int   g_boff[SCAN_BLOCKS];

__device__ __forceinline__ uint32_t f2tf32(float f) {
    uint32_t r;
    asm("cvt.rna.tf32.f32 %0, %1;" : "=r"(r) : "f"(f));
    return r;
}

// ---------------------------------------------------------------------------
// Degree / CSR build
// ---------------------------------------------------------------------------
__global__ void k_zero_cnt(int* cnt, int n) {
    int i = blockIdx.x * blockDim.x + threadIdx.x;
    if (i < n) cnt[i] = 0;
}
__global__ void k_count(const int* __restrict__ dst, int E, int* cnt) {
    int e = blockIdx.x * blockDim.x + threadIdx.x;
    if (e < E) atomicAdd(&cnt[dst[e]], 1);
}
__global__ void k_dinv(const int* __restrict__ cnt, float* __restrict__ dinv, int n) {
    int i = blockIdx.x * blockDim.x + threadIdx.x;
    if (i < n) dinv[i] = rsqrtf((float)(cnt[i] + 1));  // +1 self-loop
}

// ---- 3-phase device-wide exclusive scan over cnt[0..n) ----
__global__ void k_scan_bsum(const int* __restrict__ cnt, int* __restrict__ bsum, int n) {
    __shared__ int wsum[32];
    int i = blockIdx.x * SCAN_T + threadIdx.x;
    int v = (i < n) ? cnt[i] : 0;
#pragma unroll
    for (int o = 16; o > 0; o >>= 1) v += __shfl_down_sync(0xffffffffu, v, o);
    int lane = threadIdx.x & 31, wid = threadIdx.x >> 5;
    if (lane == 0) wsum[wid] = v;
    __syncthreads();
    if (wid == 0) {
        int w = (lane < SCAN_T / 32) ? wsum[lane] : 0;
#pragma unroll
        for (int o = 16; o > 0; o >>= 1) w += __shfl_down_sync(0xffffffffu, w, o);
        if (lane == 0) bsum[blockIdx.x] = w;
    }
}

__global__ void k_scan_boff(const int* __restrict__ bsum, int* __restrict__ boff,
                            int nblocks, int* __restrict__ row_n, int total) {
    __shared__ int wsum[32];
    int tid = threadIdx.x;
    int v = (tid < nblocks) ? bsum[tid] : 0;
    int lane = tid & 31, wid = tid >> 5;
    int s = v;
#pragma unroll
    for (int o = 1; o < 32; o <<= 1) {
        int t = __shfl_up_sync(0xffffffffu, s, o);
        if (lane >= o) s += t;
    }
    if (lane == 31) wsum[wid] = s;
    __syncthreads();
    if (wid == 0) {
        int w = (lane < SCAN_T / 32) ? wsum[lane] : 0;
#pragma unroll
        for (int o = 1; o < 32; o <<= 1) {
            int t = __shfl_up_sync(0xffffffffu, w, o);
            if (lane >= o) w += t;
        }
        wsum[lane] = w;
    }
    __syncthreads();
    int excl = (s - v) + (wid ? wsum[wid - 1] : 0);
    if (tid < nblocks) boff[tid] = excl;
    if (tid == 0) *row_n = total;
}

__global__ void k_scan_final(const int* __restrict__ cnt, const int* __restrict__ boff,
                             int* __restrict__ row_start, int* __restrict__ cursor, int n) {
    __shared__ int wsum[32];
    int i = blockIdx.x * SCAN_T + threadIdx.x;
    int v = (i < n) ? cnt[i] : 0;
    int lane = threadIdx.x & 31, wid = threadIdx.x >> 5;
    int s = v;
#pragma unroll
    for (int o = 1; o < 32; o <<= 1) {
        int t = __shfl_up_sync(0xffffffffu, s, o);
        if (lane >= o) s += t;
    }
    if (lane == 31) wsum[wid] = s;
    __syncthreads();
    if (wid == 0) {
        int w = (lane < SCAN_T / 32) ? wsum[lane] : 0;
#pragma unroll
        for (int o = 1; o < 32; o <<= 1) {
            int t = __shfl_up_sync(0xffffffffu, w, o);
            if (lane >= o) w += t;
        }
        wsum[lane] = w;
    }
    __syncthreads();
    int excl = (s - v) + (wid ? wsum[wid - 1] : 0) + boff[blockIdx.x];
    if (i < n) {
        row_start[i] = excl;
        cursor[i]    = excl;
    }
}

__global__ void k_fill(const int* __restrict__ src, const int* __restrict__ dst,
                       int E, int* __restrict__ cursor, int* __restrict__ csr) {
    int e = blockIdx.x * blockDim.x + threadIdx.x;
    if (e >= E) return;
    int d = dst[e];
    int pos = atomicAdd(&cursor[d], 1);
    csr[pos] = src[e];
}

// ---------------------------------------------------------------------------
// tf32 tensor-core GEMM, smem pre-converted to tf32.
//   C[M, N] = (A[M, K] @ B[K, N]) * rowscale[r]
// Block tile BMxBNx32, 256 threads = 8 warps laid out 4 (rows) x 2 (cols).
// Warp tile 32 x (BN/2) via 2 x (BN/16) m16n8k8 mma tiles.
// ---------------------------------------------------------------------------
template <int BN, int K>
__global__ void __launch_bounds__(256)
k_gemm_tf32(const float* __restrict__ A, const float* __restrict__ B,
            float* __restrict__ C, const float* __restrict__ rowscale, int M) {
    constexpr int BM = 128;
    constexpr int BK = 32;
    constexpr int NI = BN / 16;             // n8-tiles per warp (8 for BN=128, 4 for BN=64)
    __shared__ uint32_t As[BM][BK + 4];     // tf32 values; stride 36
    __shared__ uint32_t Bs[BK][BN + 4];     // tf32 values

    const int tid  = threadIdx.x;
    const int lane = tid & 31;
    const int wid  = tid >> 5;
    const int wrow = wid & 3;               // 32-row slice
    const int wcol = wid >> 2;              // (BN/2)-col slice
    const int rowBase = blockIdx.x * BM;

    float c[2][NI][4];
#pragma unroll
    for (int mi = 0; mi < 2; mi++)
#pragma unroll
        for (int ni = 0; ni < NI; ni++)
#pragma unroll
            for (int r = 0; r < 4; r++) c[mi][ni][r] = 0.0f;

    const int lq = lane >> 2;               // 0..7
    const int lr = lane & 3;                // 0..3

    for (int k0 = 0; k0 < K; k0 += BK) {
        // A tile BM x BK: 1024 float4-slots / 256 threads = 4 iters
#pragma unroll
        for (int it = 0; it < 4; it++) {
            int idx = tid + it * 256;
            int r  = idx >> 3;              // BK/4 = 8 float4 per row
            int c4 = idx & 7;
            float4 v = make_float4(0.f, 0.f, 0.f, 0.f);
            int gr = rowBase + r;
            if (gr < M)
                v = *reinterpret_cast<const float4*>(&A[(size_t)gr * K + k0 + c4 * 4]);
            As[r][c4 * 4 + 0] = f2tf32(v.x);
            As[r][c4 * 4 + 1] = f2tf32(v.y);
            As[r][c4 * 4 + 2] = f2tf32(v.z);
            As[r][c4 * 4 + 3] = f2tf32(v.w);
        }
        // B tile BK x BN: (BK*BN/4) float4-slots
#pragma unroll
        for (int it = 0; it < (BK * BN / 4) / 256; it++) {
            int idx = tid + it * 256;
            int r  = idx / (BN / 4);
            int c4 = idx % (BN / 4);
            float4 v = *reinterpret_cast<const float4*>(&B[(size_t)(k0 + r) * BN + c4 * 4]);
            Bs[r][c4 * 4 + 0] = f2tf32(v.x);
            Bs[r][c4 * 4 + 1] = f2tf32(v.y);
            Bs[r][c4 * 4 + 2] = f2tf32(v.z);
            Bs[r][c4 * 4 + 3] = f2tf32(v.w);
        }
        __syncthreads();

#pragma unroll
        for (int kk = 0; kk < BK; kk += 8) {
            uint32_t a[2][4];
#pragma unroll
            for (int mi = 0; mi < 2; mi++) {
                int rb = wrow * 32 + mi * 16;
                a[mi][0] = As[rb + lq    ][kk + lr    ];
                a[mi][1] = As[rb + lq + 8][kk + lr    ];
                a[mi][2] = As[rb + lq    ][kk + lr + 4];
                a[mi][3] = As[rb + lq + 8][kk + lr + 4];
            }
            uint32_t b[NI][2];
#pragma unroll
            for (int ni = 0; ni < NI; ni++) {
                int cb = wcol * (BN / 2) + ni * 8;
                b[ni][0] = Bs[kk + lr    ][cb + lq];
                b[ni][1] = Bs[kk + lr + 4][cb + lq];
            }
#pragma unroll
            for (int mi = 0; mi < 2; mi++)
#pragma unroll
                for (int ni = 0; ni < NI; ni++) {
                    asm volatile(
                        "mma.sync.aligned.m16n8k8.row.col.f32.tf32.tf32.f32 "
                        "{%0,%1,%2,%3}, {%4,%5,%6,%7}, {%8,%9}, {%0,%1,%2,%3};"
                        : "+f"(c[mi][ni][0]), "+f"(c[mi][ni][1]),
                          "+f"(c[mi][ni][2]), "+f"(c[mi][ni][3])
                        : "r"(a[mi][0]), "r"(a[mi][1]), "r"(a[mi][2]), "r"(a[mi][3]),
                          "r"(b[ni][0]), "r"(b[ni][1]));
                }
        }
        __syncthreads();
    }

    // Epilogue: per m16n8 fragment:
    //   c0,c1: row = rb + lq,     cols = cb + lr*2 + {0,1}
    //   c2,c3: row = rb + lq + 8, same cols
#pragma unroll
    for (int mi = 0; mi < 2; mi++) {
        int rb = rowBase + wrow * 32 + mi * 16;
        int r0 = rb + lq;
        int r1 = rb + lq + 8;
        float s0 = (r0 < M) ? rowscale[r0] : 0.0f;
        float s1 = (r1 < M) ? rowscale[r1] : 0.0f;
#pragma unroll
        for (int ni = 0; ni < NI; ni++) {
            int cb = wcol * (BN / 2) + ni * 8 + lr * 2;
            if (r0 < M) {
                float2 v0 = make_float2(c[mi][ni][0] * s0, c[mi][ni][1] * s0);
                *reinterpret_cast<float2*>(&C[(size_t)r0 * BN + cb]) = v0;
            }
            if (r1 < M) {
                float2 v1 = make_float2(c[mi][ni][2] * s1, c[mi][ni][3] * s1);
                *reinterpret_cast<float2*>(&C[(size_t)r1 * BN + cb]) = v1;
            }
        }
    }
}

// ---------------------------------------------------------------------------
// CSR gather-aggregate: one warp per node, VEC floats per lane (F = 32*VEC)
//   out[n] = dinv[n] * ( sum_{e} hs[csr[e]] + hs[n] ) + bias   [relu]
// ---------------------------------------------------------------------------
template <int VEC, bool RELU>
__global__ void k_agg_csr(const float* __restrict__ hs, const int* __restrict__ row_start,
                          const int* __restrict__ csr, const float* __restrict__ dinv,
                          const float* __restrict__ bias, float* __restrict__ out, int n) {
    constexpr int F = 32 * VEC;
    int warp = (blockIdx.x * blockDim.x + threadIdx.x) >> 5;
    int lane = threadIdx.x & 31;
    if (warp >= n) return;

    int e0 = row_start[warp];
    int e1 = row_start[warp + 1];

    float acc[VEC];
    if (VEC == 4) {
        float4 v = *reinterpret_cast<const float4*>(hs + (size_t)warp * F + lane * 4);
        acc[0] = v.x; acc[1] = v.y; acc[2] = v.z; acc[3] = v.w;
    } else {
        float2 v = *reinterpret_cast<const float2*>(hs + (size_t)warp * F + lane * 2);
        acc[0] = v.x; acc[1] = v.y;
    }

    int e = e0;
    for (; e + 4 <= e1; e += 4) {
        int s0 = csr[e], s1 = csr[e + 1], s2 = csr[e + 2], s3 = csr[e + 3];
        if (VEC == 4) {
            float4 v0 = *reinterpret_cast<const float4*>(hs + (size_t)s0 * F + lane * 4);
            float4 v1 = *reinterpret_cast<const float4*>(hs + (size_t)s1 * F + lane * 4);
            float4 v2 = *reinterpret_cast<const float4*>(hs + (size_t)s2 * F + lane * 4);
            float4 v3 = *reinterpret_cast<const float4*>(hs + (size_t)s3 * F + lane * 4);
            acc[0] += v0.x + v1.x + v2.x + v3.x;
            acc[1] += v0.y + v1.y + v2.y + v3.y;
            acc[2] += v0.z + v1.z + v2.z + v3.z;
            acc[3] += v0.w + v1.w + v2.w + v3.w;
        } else {
            float2 v0 = *reinterpret_cast<const float2*>(hs + (size_t)s0 * F + lane * 2);
            float2 v1 = *reinterpret_cast<const float2*>(hs + (size_t)s1 * F + lane * 2);
            float2 v2 = *reinterpret_cast<const float2*>(hs + (size_t)s2 * F + lane * 2);
            float2 v3 = *reinterpret_cast<const float2*>(hs + (size_t)s3 * F + lane * 2);
            acc[0] += v0.x + v1.x + v2.x + v3.x;
            acc[1] += v0.y + v1.y + v2.y + v3.y;
        }
    }
    for (; e < e1; e++) {
        int s = csr[e];
        if (VEC == 4) {
            float4 v = *reinterpret_cast<const float4*>(hs + (size_t)s * F + lane * 4);
            acc[0] += v.x; acc[1] += v.y; acc[2] += v.z; acc[3] += v.w;
        } else {
            float2 v = *reinterpret_cast<const float2*>(hs + (size_t)s * F + lane * 2);
            acc[0] += v.x; acc[1] += v.y;
        }
    }

    float dn = dinv[warp];
    float* op = out + (size_t)warp * F + lane * VEC;
    if (VEC == 4) {
        float4 bsv = *reinterpret_cast<const float4*>(bias + lane * 4);
        float4 r = make_float4(acc[0] * dn + bsv.x, acc[1] * dn + bsv.y,
                               acc[2] * dn + bsv.z, acc[3] * dn + bsv.w);
        if (RELU) {
            r.x = fmaxf(r.x, 0.f); r.y = fmaxf(r.y, 0.f);
            r.z = fmaxf(r.z, 0.f); r.w = fmaxf(r.w, 0.f);
        }
        *reinterpret_cast<float4*>(op) = r;
    } else {
        float2 bsv = *reinterpret_cast<const float2*>(bias + lane * 2);
        float2 r = make_float2(acc[0] * dn + bsv.x, acc[1] * dn + bsv.y);
        if (RELU) { r.x = fmaxf(r.x, 0.f); r.y = fmaxf(r.y, 0.f); }
        *reinterpret_cast<float2*>(op) = r;
    }
}

// ---------------------------------------------------------------------------
// Launcher — bind inputs BY ELEMENT COUNT
// ---------------------------------------------------------------------------
extern "C" void kernel_launch(void* const* d_in, const int* in_sizes, int n_in,
                              void* d_out, int out_size) {
    const float* x  = nullptr;
    const int*   ei = nullptr;
    const float* W1 = nullptr;
    const float* b1 = nullptr;
    const float* W2 = nullptr;
    const float* b2 = nullptr;

    for (int i = 0; i < n_in; i++) {
        switch (in_sizes[i]) {
            case N_NODES * F0:  x  = (const float*)d_in[i]; break;
            case 2 * N_EDGES:   ei = (const int*)  d_in[i]; break;
            case F0 * F1:       W1 = (const float*)d_in[i]; break;
            case F1:            b1 = (const float*)d_in[i]; break;
            case F1 * F2:       W2 = (const float*)d_in[i]; break;
            case F2:            b2 = (const float*)d_in[i]; break;
            default: break;
        }
    }

    float* out = (float*)d_out;
    const int N = N_NODES;
    const int E = N_EDGES;
    const int* src = ei;
    const int* dst = ei + E;

    float *h1s, *r1, *h2s, *dinv;
    int *cnt, *row, *cur, *csr, *bsum, *boff;
    cudaGetSymbolAddress((void**)&h1s, g_h1s);
    cudaGetSymbolAddress((void**)&r1,  g_r1);
    cudaGetSymbolAddress((void**)&h2s, g_h2s);
    cudaGetSymbolAddress((void**)&dinv, g_dinv);
    cudaGetSymbolAddress((void**)&cnt, g_cnt);
    cudaGetSymbolAddress((void**)&row, g_row);
    cudaGetSymbolAddress((void**)&cur, g_cur);
    cudaGetSymbolAddress((void**)&csr, g_csr);
    cudaGetSymbolAddress((void**)&bsum, g_bsum);
    cudaGetSymbolAddress((void**)&boff, g_boff);

    const int T = 256;

    // 1) degree histogram -> dinv, CSR row offsets (3-phase scan) + fill
    k_zero_cnt<<<(N + T - 1) / T, T>>>(cnt, N);
    k_count<<<(E + T - 1) / T, T>>>(dst, E, cnt);
    k_dinv<<<(N + T - 1) / T, T>>>(cnt, dinv, N);
    k_scan_bsum<<<SCAN_BLOCKS, SCAN_T>>>(cnt, bsum, N);
    k_scan_boff<<<1, SCAN_T>>>(bsum, boff, SCAN_BLOCKS, &row[N], E);
    k_scan_final<<<SCAN_BLOCKS, SCAN_T>>>(cnt, boff, row, cur, N);
    k_fill<<<(E + T - 1) / T, T>>>(src, dst, E, cur, csr);

    // 2) GEMM1 (tf32): h1s = (x @ W1) * dinv[row]
    k_gemm_tf32<F1, F0><<<(N + 127) / 128, 256>>>(x, W1, h1s, dinv, N);

    // 3) layer-1 aggregate + bias + relu  -> r1
    {
        int blocks = (N * 32 + T - 1) / T;
        k_agg_csr<4, true><<<blocks, T>>>(h1s, row, csr, dinv, b1, r1, N);
    }

    // 4) GEMM2 (tf32): h2s = (r1 @ W2) * dinv[row]
    k_gemm_tf32<F2, F1><<<(N + 127) / 128, 256>>>(r1, W2, h2s, dinv, N);

    // 5) layer-2 aggregate + bias -> out
    {
        int blocks = (N * 32 + T - 1) / T;
        k_agg_csr<2, false><<<blocks, T>>>(h2s, row, csr, dinv, b2, out, N);
    }
}